// round 1
// baseline (speedup 1.0000x reference)
#include <cuda_runtime.h>
#include <cuda_bf16.h>
#include <math.h>

#define NU 100000
#define NR 50000
#define NE 600000
#define NL 200000
#define HD 128
#define OD 64

// ---------------- scratch (static device globals; no allocation) ----------------
__device__ __align__(16) float g_hu[(size_t)NU * HD];
__device__ __align__(16) float g_hr[(size_t)NR * HD];
__device__ __align__(16) float g_u1[(size_t)NU * HD];
__device__ __align__(16) float g_r1[(size_t)NR * HD];
__device__ __align__(16) float g_mean_u[(size_t)NU * HD];
__device__ __align__(16) float g_mean_r[(size_t)NR * HD];
__device__ __align__(16) float g_zu[(size_t)NU * OD];
__device__ __align__(16) float g_zr[(size_t)NR * OD];

__device__ int g_deg_r[NR];
__device__ int g_deg_u[NU];
__device__ int g_off_r[NR + 1];
__device__ int g_off_u[NU + 1];
__device__ int g_cur_r[NR];
__device__ int g_cur_u[NU];
__device__ int g_csr_r[NE];   // for each recipe, list of user neighbors
__device__ int g_csr_u[NE];   // for each user, list of recipe neighbors

// ---------------- CSR build ----------------
__global__ void count_kernel(const int* __restrict__ es, const int* __restrict__ ed,
                             int* __restrict__ deg_u, int* __restrict__ deg_r, int E)
{
    int t = blockIdx.x * blockDim.x + threadIdx.x;
    if (t < E) {
        atomicAdd(&deg_u[es[t]], 1);
        atomicAdd(&deg_r[ed[t]], 1);
    }
}

// single-block exclusive scan: deg[0..n) -> off[0..n], also copies to cursor
__global__ void scan_kernel(const int* __restrict__ deg, int* __restrict__ off,
                            int* __restrict__ cur, int n)
{
    __shared__ int tmp[1024];
    int t = threadIdx.x;
    int chunk = (n + 1023) / 1024;
    int start = t * chunk;
    int end = min(start + chunk, n);
    if (start > n) start = n;
    int s = 0;
    for (int i = start; i < end; i++) s += deg[i];
    tmp[t] = s;
    __syncthreads();
    for (int d = 1; d < 1024; d <<= 1) {
        int v = (t >= d) ? tmp[t - d] : 0;
        __syncthreads();
        tmp[t] += v;
        __syncthreads();
    }
    int base = (t == 0) ? 0 : tmp[t - 1];
    int run = base;
    for (int i = start; i < end; i++) {
        off[i] = run;
        cur[i] = run;
        run += deg[i];
    }
    if (end == n) off[n] = run;
}

__global__ void fill_kernel(const int* __restrict__ es, const int* __restrict__ ed,
                            int* __restrict__ cur_u, int* __restrict__ cur_r,
                            int* __restrict__ csr_u, int* __restrict__ csr_r, int E)
{
    int t = blockIdx.x * blockDim.x + threadIdx.x;
    if (t < E) {
        int s = es[t], d = ed[t];
        int pr = atomicAdd(&cur_r[d], 1);
        csr_r[pr] = s;
        int pu = atomicAdd(&cur_u[s], 1);
        csr_u[pu] = d;
    }
}

// ---------------- gather-mean: one warp per destination node ----------------
__global__ __launch_bounds__(256) void gather_mean_kernel(
    const float4* __restrict__ feat, const int* __restrict__ off,
    const int* __restrict__ csr, float4* __restrict__ outm, int n)
{
    int warp = (blockIdx.x * blockDim.x + threadIdx.x) >> 5;
    int lane = threadIdx.x & 31;
    if (warp >= n) return;
    int b = off[warp], e = off[warp + 1];
    float4 acc = make_float4(0.f, 0.f, 0.f, 0.f);
    for (int i = b; i < e; i++) {
        int nb = csr[i];
        float4 v = feat[(size_t)nb * 32 + lane];
        acc.x += v.x; acc.y += v.y; acc.z += v.z; acc.w += v.w;
    }
    float inv = 1.f / fmaxf((float)(e - b), 1.f);
    acc.x *= inv; acc.y *= inv; acc.z *= inv; acc.w *= inv;
    outm[(size_t)warp * 32 + lane] = acc;
}

// ---------------- GEMM: Y[M,N] = A@Wl^T + bl (+ X@Wr^T) (+relu) ----------------
// 256 threads, 64 rows per block. Weights staged in smem with pitch K+1 (odd
// -> conflict-free column loads). A rows read as lane-uniform LDS broadcasts.
template <int N, int K, bool RELU, bool DUAL>
__global__ __launch_bounds__(256) void gemm_kernel(
    const float* __restrict__ A, const float* __restrict__ X,
    const float* __restrict__ Wl, const float* __restrict__ bl,
    const float* __restrict__ Wr, float* __restrict__ Y, int M)
{
    constexpr int PK = K + 1;
    constexpr int CPT = N / 32;   // columns per thread (stride 32)
    extern __shared__ float sm[];
    float* sWl = sm;                                  // N*PK
    float* sWr = sm + N * PK;                         // N*PK (DUAL)
    float* sA  = sm + (DUAL ? 2 : 1) * N * PK;        // 64*K
    float* sX  = sA + 64 * K;                         // 64*K (DUAL)

    const int tid = threadIdx.x;
    const int row0 = blockIdx.x * 64;

    for (int idx = tid; idx < N * K; idx += 256) {
        int c = idx / K, k = idx - c * K;
        sWl[c * PK + k] = Wl[idx];
        if (DUAL) sWr[c * PK + k] = Wr[idx];
    }
    for (int idx = tid; idx < 64 * K; idx += 256) {
        int r = idx / K, k = idx - r * K;
        int row = row0 + r;
        float va = 0.f, vx = 0.f;
        if (row < M) {
            va = A[(size_t)row * K + k];
            if (DUAL) vx = X[(size_t)row * K + k];
        }
        sA[r * K + k] = va;
        if (DUAL) sX[r * K + k] = vx;
    }
    __syncthreads();

    const int lane = tid & 31;
    const int w = tid >> 5;
    const int r0 = w * 8;

    float acc[8][CPT];
#pragma unroll
    for (int i = 0; i < 8; i++)
#pragma unroll
        for (int j = 0; j < CPT; j++) acc[i][j] = 0.f;

#pragma unroll 4
    for (int k = 0; k < K; k++) {
        float a[8];
#pragma unroll
        for (int i = 0; i < 8; i++) a[i] = sA[(r0 + i) * K + k];
        float wl[CPT];
#pragma unroll
        for (int j = 0; j < CPT; j++) wl[j] = sWl[(lane + j * 32) * PK + k];
#pragma unroll
        for (int i = 0; i < 8; i++)
#pragma unroll
            for (int j = 0; j < CPT; j++) acc[i][j] += a[i] * wl[j];
        if (DUAL) {
            float x[8];
#pragma unroll
            for (int i = 0; i < 8; i++) x[i] = sX[(r0 + i) * K + k];
            float wr[CPT];
#pragma unroll
            for (int j = 0; j < CPT; j++) wr[j] = sWr[(lane + j * 32) * PK + k];
#pragma unroll
            for (int i = 0; i < 8; i++)
#pragma unroll
                for (int j = 0; j < CPT; j++) acc[i][j] += x[i] * wr[j];
        }
    }

#pragma unroll
    for (int i = 0; i < 8; i++) {
        int row = row0 + r0 + i;
        if (row < M) {
#pragma unroll
            for (int j = 0; j < CPT; j++) {
                int c = lane + j * 32;
                float v = acc[i][j] + bl[c];
                if (RELU) v = fmaxf(v, 0.f);
                Y[(size_t)row * N + c] = v;
            }
        }
    }
}

// ---------------- decoder: warp per label pair ----------------
__global__ __launch_bounds__(256) void decode_kernel(
    const float* __restrict__ zu, const float* __restrict__ zr,
    const int* __restrict__ ls, const int* __restrict__ ld,
    float* __restrict__ out, int L)
{
    int warp = (blockIdx.x * blockDim.x + threadIdx.x) >> 5;
    int lane = threadIdx.x & 31;
    if (warp >= L) return;
    int s = ls[warp], d = ld[warp];
    float a0 = zu[(size_t)s * 64 + lane];
    float a1 = zu[(size_t)s * 64 + 32 + lane];
    float b0 = zr[(size_t)d * 64 + lane];
    float b1 = zr[(size_t)d * 64 + 32 + lane];
    float dot = a0 * b0 + a1 * b1;
    float na = a0 * a0 + a1 * a1;
    float nb = b0 * b0 + b1 * b1;
#pragma unroll
    for (int o = 16; o; o >>= 1) {
        dot += __shfl_xor_sync(0xffffffffu, dot, o);
        na  += __shfl_xor_sync(0xffffffffu, na, o);
        nb  += __shfl_xor_sync(0xffffffffu, nb, o);
    }
    if (lane == 0)
        out[warp] = dot / (fmaxf(sqrtf(na), 1e-12f) * fmaxf(sqrtf(nb), 1e-12f));
}

// ---------------- host launch ----------------
extern "C" void kernel_launch(void* const* d_in, const int* in_sizes, int n_in,
                              void* d_out, int out_size)
{
    const float* x_user   = (const float*)d_in[0];
    const float* x_recipe = (const float*)d_in[1];
    const int* edge_src   = (const int*)d_in[2];
    const int* edge_dst   = (const int*)d_in[3];
    const int* lbl_src    = (const int*)d_in[4];
    const int* lbl_dst    = (const int*)d_in[5];
    const float* Wu   = (const float*)d_in[6];
    const float* bu   = (const float*)d_in[7];
    const float* Wrec = (const float*)d_in[8];
    const float* brec = (const float*)d_in[9];
    const float* c1_ur_Wl = (const float*)d_in[10];
    const float* c1_ur_bl = (const float*)d_in[11];
    const float* c1_ur_Wr = (const float*)d_in[12];
    const float* c1_ru_Wl = (const float*)d_in[13];
    const float* c1_ru_bl = (const float*)d_in[14];
    const float* c1_ru_Wr = (const float*)d_in[15];
    const float* c2_ur_Wl = (const float*)d_in[16];
    const float* c2_ur_bl = (const float*)d_in[17];
    const float* c2_ur_Wr = (const float*)d_in[18];
    const float* c2_ru_Wl = (const float*)d_in[19];
    const float* c2_ru_bl = (const float*)d_in[20];
    const float* c2_ru_Wr = (const float*)d_in[21];
    float* out = (float*)d_out;

    float *hu, *hr, *u1, *r1, *mu, *mr, *zu, *zr;
    int *deg_r, *deg_u, *off_r, *off_u, *cur_r, *cur_u, *csr_r, *csr_u;
    cudaGetSymbolAddress((void**)&hu, g_hu);
    cudaGetSymbolAddress((void**)&hr, g_hr);
    cudaGetSymbolAddress((void**)&u1, g_u1);
    cudaGetSymbolAddress((void**)&r1, g_r1);
    cudaGetSymbolAddress((void**)&mu, g_mean_u);
    cudaGetSymbolAddress((void**)&mr, g_mean_r);
    cudaGetSymbolAddress((void**)&zu, g_zu);
    cudaGetSymbolAddress((void**)&zr, g_zr);
    cudaGetSymbolAddress((void**)&deg_r, g_deg_r);
    cudaGetSymbolAddress((void**)&deg_u, g_deg_u);
    cudaGetSymbolAddress((void**)&off_r, g_off_r);
    cudaGetSymbolAddress((void**)&off_u, g_off_u);
    cudaGetSymbolAddress((void**)&cur_r, g_cur_r);
    cudaGetSymbolAddress((void**)&cur_u, g_cur_u);
    cudaGetSymbolAddress((void**)&csr_r, g_csr_r);
    cudaGetSymbolAddress((void**)&csr_u, g_csr_u);

    // dynamic smem opt-in (bytes)
    const int S_LIN128  = (128 * 129 + 64 * 128) * 4;            // 98816
    const int S_LIN256  = (128 * 257 + 64 * 256) * 4;            // 197120
    const int S_DUAL128 = (2 * 128 * 129 + 2 * 64 * 128) * 4;    // 197632
    const int S_DUAL64  = (2 * 64 * 129 + 2 * 64 * 128) * 4;     // 131584
    cudaFuncSetAttribute(gemm_kernel<128, 128, false, false>,
                         cudaFuncAttributeMaxDynamicSharedMemorySize, S_LIN128);
    cudaFuncSetAttribute(gemm_kernel<128, 256, false, false>,
                         cudaFuncAttributeMaxDynamicSharedMemorySize, S_LIN256);
    cudaFuncSetAttribute(gemm_kernel<128, 128, true, true>,
                         cudaFuncAttributeMaxDynamicSharedMemorySize, S_DUAL128);
    cudaFuncSetAttribute(gemm_kernel<64, 128, false, true>,
                         cudaFuncAttributeMaxDynamicSharedMemorySize, S_DUAL64);

    // ---- CSR build (same for both convs) ----
    cudaMemsetAsync(deg_r, 0, NR * sizeof(int), 0);
    cudaMemsetAsync(deg_u, 0, NU * sizeof(int), 0);
    count_kernel<<<(NE + 255) / 256, 256>>>(edge_src, edge_dst, deg_u, deg_r, NE);
    scan_kernel<<<1, 1024>>>(deg_r, off_r, cur_r, NR);
    scan_kernel<<<1, 1024>>>(deg_u, off_u, cur_u, NU);
    fill_kernel<<<(NE + 255) / 256, 256>>>(edge_src, edge_dst, cur_u, cur_r,
                                           csr_u, csr_r, NE);

    // ---- input projections ----
    gemm_kernel<128, 128, false, false><<<(NU + 63) / 64, 256, S_LIN128>>>(
        x_user, nullptr, Wu, bu, nullptr, hu, NU);
    gemm_kernel<128, 256, false, false><<<(NR + 63) / 64, 256, S_LIN256>>>(
        x_recipe, nullptr, Wrec, brec, nullptr, hr, NR);

    // ---- conv1 ----
    gather_mean_kernel<<<(NR * 32 + 255) / 256, 256>>>(
        (const float4*)hu, off_r, csr_r, (float4*)mr, NR);
    gather_mean_kernel<<<(NU * 32 + 255) / 256, 256>>>(
        (const float4*)hr, off_u, csr_u, (float4*)mu, NU);
    gemm_kernel<128, 128, true, true><<<(NR + 63) / 64, 256, S_DUAL128>>>(
        mr, hr, c1_ur_Wl, c1_ur_bl, c1_ur_Wr, r1, NR);
    gemm_kernel<128, 128, true, true><<<(NU + 63) / 64, 256, S_DUAL128>>>(
        mu, hu, c1_ru_Wl, c1_ru_bl, c1_ru_Wr, u1, NU);

    // ---- conv2 ----
    gather_mean_kernel<<<(NR * 32 + 255) / 256, 256>>>(
        (const float4*)u1, off_r, csr_r, (float4*)mr, NR);
    gather_mean_kernel<<<(NU * 32 + 255) / 256, 256>>>(
        (const float4*)r1, off_u, csr_u, (float4*)mu, NU);
    gemm_kernel<64, 128, false, true><<<(NR + 63) / 64, 256, S_DUAL64>>>(
        mr, r1, c2_ur_Wl, c2_ur_bl, c2_ur_Wr, zr, NR);
    gemm_kernel<64, 128, false, true><<<(NU + 63) / 64, 256, S_DUAL64>>>(
        mu, u1, c2_ru_Wl, c2_ru_bl, c2_ru_Wr, zu, NU);

    // ---- decoder ----
    decode_kernel<<<(NL * 32 + 255) / 256, 256>>>(zu, zr, lbl_src, lbl_dst, out, NL);
}

// round 2
// speedup vs baseline: 1.1144x; 1.1144x over previous
#include <cuda_runtime.h>
#include <cuda_bf16.h>
#include <math.h>

#define NU 100000
#define NR 50000
#define NE 600000
#define NL 200000
#define HD 128
#define OD 64

typedef unsigned long long u64;

// ---------------- f32x2 packed math ----------------
__device__ __forceinline__ u64 fma2(u64 a, u64 b, u64 c) {
    u64 d;
    asm("fma.rn.f32x2 %0, %1, %2, %3;" : "=l"(d) : "l"(a), "l"(b), "l"(c));
    return d;
}
__device__ __forceinline__ u64 pack2(float x, float y) {
    u64 d; asm("mov.b64 %0, {%1, %2};" : "=l"(d) : "f"(x), "f"(y)); return d;
}
__device__ __forceinline__ float2 unpack2(u64 v) {
    float2 r; asm("mov.b64 {%0, %1}, %2;" : "=f"(r.x), "=f"(r.y) : "l"(v)); return r;
}

// ---------------- scratch (static device globals) ----------------
__device__ __align__(16) float g_hu[(size_t)NU * HD];
__device__ __align__(16) float g_hr[(size_t)NR * HD];
__device__ __align__(16) float g_u1[(size_t)NU * HD];
__device__ __align__(16) float g_r1[(size_t)NR * HD];
__device__ __align__(16) float g_mean_u[(size_t)NU * HD];
__device__ __align__(16) float g_mean_r[(size_t)NR * HD];
__device__ __align__(16) float g_zu[(size_t)NU * OD];
__device__ __align__(16) float g_zr[(size_t)NR * OD];
__device__ __align__(16) float g_wt[147456];   // transposed weights

__device__ int g_deg_r[NR];
__device__ int g_deg_u[NU];
__device__ int g_off_r[NR + 1];
__device__ int g_off_u[NU + 1];
__device__ int g_cur_r[NR];
__device__ int g_cur_u[NU];
__device__ int g_csr_r[NE];
__device__ int g_csr_u[NE];

// transposed-weight offsets (floats) inside g_wt
#define WT_WU      0
#define WT_WREC    16384
#define WT_C1URWL  49152
#define WT_C1URWR  65536
#define WT_C1RUWL  81920
#define WT_C1RUWR  98304
#define WT_C2URWL  114688
#define WT_C2URWR  122880
#define WT_C2RUWL  131072
#define WT_C2RUWR  139264

// ---------------- CSR build ----------------
__global__ void count_kernel(const int* __restrict__ es, const int* __restrict__ ed,
                             int* __restrict__ deg_u, int* __restrict__ deg_r, int E)
{
    int t = blockIdx.x * blockDim.x + threadIdx.x;
    if (t < E) {
        atomicAdd(&deg_u[es[t]], 1);
        atomicAdd(&deg_r[ed[t]], 1);
    }
}

__global__ void scan_kernel(const int* __restrict__ deg, int* __restrict__ off,
                            int* __restrict__ cur, int n)
{
    __shared__ int tmp[1024];
    int t = threadIdx.x;
    int chunk = (n + 1023) / 1024;
    int start = t * chunk;
    int end = min(start + chunk, n);
    if (start > n) start = n;
    int s = 0;
    for (int i = start; i < end; i++) s += deg[i];
    tmp[t] = s;
    __syncthreads();
    for (int d = 1; d < 1024; d <<= 1) {
        int v = (t >= d) ? tmp[t - d] : 0;
        __syncthreads();
        tmp[t] += v;
        __syncthreads();
    }
    int base = (t == 0) ? 0 : tmp[t - 1];
    int run = base;
    for (int i = start; i < end; i++) {
        off[i] = run;
        cur[i] = run;
        run += deg[i];
    }
    if (end == n) off[n] = run;
}

__global__ void fill_kernel(const int* __restrict__ es, const int* __restrict__ ed,
                            int* __restrict__ cur_u, int* __restrict__ cur_r,
                            int* __restrict__ csr_u, int* __restrict__ csr_r, int E)
{
    int t = blockIdx.x * blockDim.x + threadIdx.x;
    if (t < E) {
        int s = es[t], d = ed[t];
        int pr = atomicAdd(&cur_r[d], 1);
        csr_r[pr] = s;
        int pu = atomicAdd(&cur_u[s], 1);
        csr_u[pu] = d;
    }
}

// ---------------- weight transpose: W[N][K] -> Wt[K][N] ----------------
struct WtArgs {
    const float* src[10];
    int n[10];
    int k[10];
    int blk_off[11];   // block-index boundaries
    int doff[10];      // dst float offsets
};

__global__ void wtrans_kernel(WtArgs a, float* __restrict__ dst)
{
    int b = blockIdx.x;
    int m = 0;
    while (b >= a.blk_off[m + 1]) m++;
    int idx = (b - a.blk_off[m]) * 256 + threadIdx.x;
    int N = a.n[m], K = a.k[m];
    if (idx < N * K) {
        int kk = idx / N, nn = idx - kk * N;
        dst[a.doff[m] + idx] = a.src[m][nn * K + kk];
    }
}

// ---------------- fused gather-mean (both directions): warp per dst node ----------------
__global__ __launch_bounds__(256) void gather2_kernel(
    const float4* __restrict__ featR, const float4* __restrict__ featU,
    const int* __restrict__ off_r, const int* __restrict__ csr_r,
    const int* __restrict__ off_u, const int* __restrict__ csr_u,
    float4* __restrict__ outR, float4* __restrict__ outU)
{
    int warp = (blockIdx.x * blockDim.x + threadIdx.x) >> 5;
    int lane = threadIdx.x & 31;
    const float4* feat;
    const int* off;
    const int* csr;
    float4* outm;
    int node;
    if (warp < NR) {
        feat = featR; off = off_r; csr = csr_r; outm = outR; node = warp;
    } else if (warp < NR + NU) {
        feat = featU; off = off_u; csr = csr_u; outm = outU; node = warp - NR;
    } else return;
    int b = off[node], e = off[node + 1];
    float4 acc = make_float4(0.f, 0.f, 0.f, 0.f);
    for (int i = b; i < e; i++) {
        int nb = csr[i];
        float4 v = feat[(size_t)nb * 32 + lane];
        acc.x += v.x; acc.y += v.y; acc.z += v.z; acc.w += v.w;
    }
    float inv = 1.f / fmaxf((float)(e - b), 1.f);
    acc.x *= inv; acc.y *= inv; acc.z *= inv; acc.w *= inv;
    outm[(size_t)node * 32 + lane] = acc;
}

// ---------------- GEMM core (f32x2): Y = A@Wl^T + bl (+ X@Wr^T)(+relu) ----------------
// Wlt/Wrt are pre-transposed [K][N]. 256 thr, 64 rows/block, warp owns 8 rows,
// thread owns CPT adjacent output columns.
template <int N, int K, bool RELU, bool DUAL>
__device__ __forceinline__ void gemm_body(
    const float* __restrict__ A, const float* __restrict__ X,
    const float* __restrict__ Wlt, const float* __restrict__ bl,
    const float* __restrict__ Wrt, float* __restrict__ Y, int M, int row0)
{
    constexpr int CPT = N / 32;        // 4 or 2
    constexpr int PAIRS = CPT / 2;     // 2 or 1
    extern __shared__ float sm[];
    float* sWl = sm;                                 // K*N
    float* sWr = sm + K * N;                         // K*N (DUAL)
    float* sA  = sm + (DUAL ? 2 : 1) * K * N;        // 64*K
    float* sX  = sA + 64 * K;                        // 64*K (DUAL)

    const int tid = threadIdx.x;

    // stage weights (coalesced read & write, already transposed)
    for (int idx = tid; idx < K * N; idx += 256) {
        sWl[idx] = Wlt[idx];
        if (DUAL) sWr[idx] = Wrt[idx];
    }
    // stage A (and X) rows [r][k], coalesced
    {
        const float* Ab = A + (size_t)row0 * K;
        const float* Xb = DUAL ? (X + (size_t)row0 * K) : nullptr;
        int lim = (min(64, M - row0)) * K;
        for (int idx = tid; idx < 64 * K; idx += 256) {
            float va = (idx < lim) ? Ab[idx] : 0.f;
            sA[idx] = va;
            if (DUAL) {
                float vx = (idx < lim) ? Xb[idx] : 0.f;
                sX[idx] = vx;
            }
        }
    }
    __syncthreads();

    const int lane = tid & 31;
    const int w = tid >> 5;
    const int r0 = w * 8;
    const int colbase = lane * CPT;

    u64 acc[8][PAIRS];
#pragma unroll
    for (int i = 0; i < 8; i++)
#pragma unroll
        for (int p = 0; p < PAIRS; p++) acc[i][p] = 0ull;

#pragma unroll 2
    for (int k0 = 0; k0 < K; k0 += 4) {
        float4 a4[8], x4[8];
#pragma unroll
        for (int i = 0; i < 8; i++) {
            a4[i] = *(const float4*)&sA[(r0 + i) * K + k0];
            if (DUAL) x4[i] = *(const float4*)&sX[(r0 + i) * K + k0];
        }
#pragma unroll
        for (int kk = 0; kk < 4; kk++) {
            u64 wl[PAIRS], wr[PAIRS];
            const float* wlp = &sWl[(k0 + kk) * N + colbase];
            if (CPT == 4) {
                float4 v = *(const float4*)wlp;
                wl[0] = pack2(v.x, v.y);
                if (PAIRS > 1) wl[1] = pack2(v.z, v.w);
            } else {
                float2 v = *(const float2*)wlp;
                wl[0] = pack2(v.x, v.y);
            }
            if (DUAL) {
                const float* wrp = &sWr[(k0 + kk) * N + colbase];
                if (CPT == 4) {
                    float4 v = *(const float4*)wrp;
                    wr[0] = pack2(v.x, v.y);
                    if (PAIRS > 1) wr[1] = pack2(v.z, v.w);
                } else {
                    float2 v = *(const float2*)wrp;
                    wr[0] = pack2(v.x, v.y);
                }
            }
#pragma unroll
            for (int i = 0; i < 8; i++) {
                float as = (kk == 0) ? a4[i].x : (kk == 1) ? a4[i].y :
                           (kk == 2) ? a4[i].z : a4[i].w;
                u64 a2 = pack2(as, as);
#pragma unroll
                for (int p = 0; p < PAIRS; p++) acc[i][p] = fma2(a2, wl[p], acc[i][p]);
                if (DUAL) {
                    float xs = (kk == 0) ? x4[i].x : (kk == 1) ? x4[i].y :
                               (kk == 2) ? x4[i].z : x4[i].w;
                    u64 x2 = pack2(xs, xs);
#pragma unroll
                    for (int p = 0; p < PAIRS; p++) acc[i][p] = fma2(x2, wr[p], acc[i][p]);
                }
            }
        }
    }

    // epilogue
    float bv[CPT];
#pragma unroll
    for (int j = 0; j < CPT; j++) bv[j] = bl[colbase + j];

#pragma unroll
    for (int i = 0; i < 8; i++) {
        int row = row0 + r0 + i;
        if (row < M) {
            float o[CPT];
#pragma unroll
            for (int p = 0; p < PAIRS; p++) {
                float2 v = unpack2(acc[i][p]);
                o[2 * p] = v.x + bv[2 * p];
                o[2 * p + 1] = v.y + bv[2 * p + 1];
            }
            if (RELU) {
#pragma unroll
                for (int j = 0; j < CPT; j++) o[j] = fmaxf(o[j], 0.f);
            }
            float* yp = &Y[(size_t)row * N + colbase];
            if (CPT == 4) *(float4*)yp = make_float4(o[0], o[1], o[2], o[3]);
            else          *(float2*)yp = make_float2(o[0], o[1]);
        }
    }
}

template <int N, int K, bool RELU>
__global__ __launch_bounds__(256) void gemm_single(
    const float* __restrict__ A, const float* __restrict__ Wlt,
    const float* __restrict__ bl, float* __restrict__ Y, int M)
{
    gemm_body<N, K, RELU, false>(A, nullptr, Wlt, bl, nullptr, Y, M, blockIdx.x * 64);
}

struct DualArgs {
    const float *A0, *X0, *Wl0, *bl0, *Wr0; float* Y0; int M0; int g0;
    const float *A1, *X1, *Wl1, *bl1, *Wr1; float* Y1; int M1;
};

// one launch covering both conv directions
template <int N, int K, bool RELU>
__global__ __launch_bounds__(256) void gemm_dual2(DualArgs d)
{
    if (blockIdx.x < (unsigned)d.g0) {
        gemm_body<N, K, RELU, true>(d.A0, d.X0, d.Wl0, d.bl0, d.Wr0, d.Y0, d.M0,
                                    blockIdx.x * 64);
    } else {
        gemm_body<N, K, RELU, true>(d.A1, d.X1, d.Wl1, d.bl1, d.Wr1, d.Y1, d.M1,
                                    (blockIdx.x - d.g0) * 64);
    }
}

// ---------------- decoder: warp per label pair ----------------
__global__ __launch_bounds__(256) void decode_kernel(
    const float* __restrict__ zu, const float* __restrict__ zr,
    const int* __restrict__ ls, const int* __restrict__ ld,
    float* __restrict__ out, int L)
{
    int warp = (blockIdx.x * blockDim.x + threadIdx.x) >> 5;
    int lane = threadIdx.x & 31;
    if (warp >= L) return;
    int s = ls[warp], d = ld[warp];
    float a0 = zu[(size_t)s * 64 + lane];
    float a1 = zu[(size_t)s * 64 + 32 + lane];
    float b0 = zr[(size_t)d * 64 + lane];
    float b1 = zr[(size_t)d * 64 + 32 + lane];
    float dot = a0 * b0 + a1 * b1;
    float na = a0 * a0 + a1 * a1;
    float nb = b0 * b0 + b1 * b1;
#pragma unroll
    for (int o = 16; o; o >>= 1) {
        dot += __shfl_xor_sync(0xffffffffu, dot, o);
        na  += __shfl_xor_sync(0xffffffffu, na, o);
        nb  += __shfl_xor_sync(0xffffffffu, nb, o);
    }
    if (lane == 0)
        out[warp] = dot / (fmaxf(sqrtf(na), 1e-12f) * fmaxf(sqrtf(nb), 1e-12f));
}

// ---------------- host launch ----------------
extern "C" void kernel_launch(void* const* d_in, const int* in_sizes, int n_in,
                              void* d_out, int out_size)
{
    const float* x_user   = (const float*)d_in[0];
    const float* x_recipe = (const float*)d_in[1];
    const int* edge_src   = (const int*)d_in[2];
    const int* edge_dst   = (const int*)d_in[3];
    const int* lbl_src    = (const int*)d_in[4];
    const int* lbl_dst    = (const int*)d_in[5];
    const float* Wu   = (const float*)d_in[6];
    const float* bu   = (const float*)d_in[7];
    const float* Wrec = (const float*)d_in[8];
    const float* brec = (const float*)d_in[9];
    const float* c1_ur_Wl = (const float*)d_in[10];
    const float* c1_ur_bl = (const float*)d_in[11];
    const float* c1_ur_Wr = (const float*)d_in[12];
    const float* c1_ru_Wl = (const float*)d_in[13];
    const float* c1_ru_bl = (const float*)d_in[14];
    const float* c1_ru_Wr = (const float*)d_in[15];
    const float* c2_ur_Wl = (const float*)d_in[16];
    const float* c2_ur_bl = (const float*)d_in[17];
    const float* c2_ur_Wr = (const float*)d_in[18];
    const float* c2_ru_Wl = (const float*)d_in[19];
    const float* c2_ru_bl = (const float*)d_in[20];
    const float* c2_ru_Wr = (const float*)d_in[21];
    float* out = (float*)d_out;

    float *hu, *hr, *u1, *r1, *mu, *mr, *zu, *zr, *wt;
    int *deg_r, *deg_u, *off_r, *off_u, *cur_r, *cur_u, *csr_r, *csr_u;
    cudaGetSymbolAddress((void**)&hu, g_hu);
    cudaGetSymbolAddress((void**)&hr, g_hr);
    cudaGetSymbolAddress((void**)&u1, g_u1);
    cudaGetSymbolAddress((void**)&r1, g_r1);
    cudaGetSymbolAddress((void**)&mu, g_mean_u);
    cudaGetSymbolAddress((void**)&mr, g_mean_r);
    cudaGetSymbolAddress((void**)&zu, g_zu);
    cudaGetSymbolAddress((void**)&zr, g_zr);
    cudaGetSymbolAddress((void**)&wt, g_wt);
    cudaGetSymbolAddress((void**)&deg_r, g_deg_r);
    cudaGetSymbolAddress((void**)&deg_u, g_deg_u);
    cudaGetSymbolAddress((void**)&off_r, g_off_r);
    cudaGetSymbolAddress((void**)&off_u, g_off_u);
    cudaGetSymbolAddress((void**)&cur_r, g_cur_r);
    cudaGetSymbolAddress((void**)&cur_u, g_cur_u);
    cudaGetSymbolAddress((void**)&csr_r, g_csr_r);
    cudaGetSymbolAddress((void**)&csr_u, g_csr_u);

    // dynamic smem (bytes)
    const int S_P128  = (128 * 128 + 64 * 128) * 4;              // 98304
    const int S_P256  = (256 * 128 + 64 * 256) * 4;              // 196608
    const int S_D128  = (2 * 128 * 128 + 2 * 64 * 128) * 4;      // 196608
    const int S_D64   = (2 * 128 * 64 + 2 * 64 * 128) * 4;       // 131072
    cudaFuncSetAttribute(gemm_single<128, 128, false>,
                         cudaFuncAttributeMaxDynamicSharedMemorySize, S_P128);
    cudaFuncSetAttribute(gemm_single<128, 256, false>,
                         cudaFuncAttributeMaxDynamicSharedMemorySize, S_P256);
    cudaFuncSetAttribute(gemm_dual2<128, 128, true>,
                         cudaFuncAttributeMaxDynamicSharedMemorySize, S_D128);
    cudaFuncSetAttribute(gemm_dual2<64, 128, false>,
                         cudaFuncAttributeMaxDynamicSharedMemorySize, S_D64);

    // ---- CSR build ----
    cudaMemsetAsync(deg_r, 0, NR * sizeof(int), 0);
    cudaMemsetAsync(deg_u, 0, NU * sizeof(int), 0);
    count_kernel<<<(NE + 255) / 256, 256>>>(edge_src, edge_dst, deg_u, deg_r, NE);
    scan_kernel<<<1, 1024>>>(deg_r, off_r, cur_r, NR);
    scan_kernel<<<1, 1024>>>(deg_u, off_u, cur_u, NU);
    fill_kernel<<<(NE + 255) / 256, 256>>>(edge_src, edge_dst, cur_u, cur_r,
                                           csr_u, csr_r, NE);

    // ---- weight transpose ----
    {
        WtArgs a;
        const float* srcs[10] = {Wu, Wrec, c1_ur_Wl, c1_ur_Wr, c1_ru_Wl, c1_ru_Wr,
                                 c2_ur_Wl, c2_ur_Wr, c2_ru_Wl, c2_ru_Wr};
        int ns[10] = {128, 128, 128, 128, 128, 128, 64, 64, 64, 64};
        int ks[10] = {128, 256, 128, 128, 128, 128, 128, 128, 128, 128};
        int doffs[10] = {WT_WU, WT_WREC, WT_C1URWL, WT_C1URWR, WT_C1RUWL, WT_C1RUWR,
                         WT_C2URWL, WT_C2URWR, WT_C2RUWL, WT_C2RUWR};
        int boff = 0;
        for (int m = 0; m < 10; m++) {
            a.src[m] = srcs[m]; a.n[m] = ns[m]; a.k[m] = ks[m]; a.doff[m] = doffs[m];
            a.blk_off[m] = boff;
            boff += (ns[m] * ks[m] + 255) / 256;
        }
        a.blk_off[10] = boff;
        wtrans_kernel<<<boff, 256>>>(a, wt);
    }

    // ---- input projections ----
    gemm_single<128, 128, false><<<(NU + 63) / 64, 256, S_P128>>>(
        x_user, wt + WT_WU, bu, hu, NU);
    gemm_single<128, 256, false><<<(NR + 63) / 64, 256, S_P256>>>(
        x_recipe, wt + WT_WREC, brec, hr, NR);

    const int GR = (NR + 63) / 64, GU = (NU + 63) / 64;
    const int GW = ((NR + NU) * 32 + 255) / 256;

    // ---- conv1 ----
    gather2_kernel<<<GW, 256>>>((const float4*)hu, (const float4*)hr,
                                off_r, csr_r, off_u, csr_u,
                                (float4*)mr, (float4*)mu);
    {
        DualArgs d;
        d.A0 = mr; d.X0 = hr; d.Wl0 = wt + WT_C1URWL; d.bl0 = c1_ur_bl;
        d.Wr0 = wt + WT_C1URWR; d.Y0 = r1; d.M0 = NR; d.g0 = GR;
        d.A1 = mu; d.X1 = hu; d.Wl1 = wt + WT_C1RUWL; d.bl1 = c1_ru_bl;
        d.Wr1 = wt + WT_C1RUWR; d.Y1 = u1; d.M1 = NU;
        gemm_dual2<128, 128, true><<<GR + GU, 256, S_D128>>>(d);
    }

    // ---- conv2 ----
    gather2_kernel<<<GW, 256>>>((const float4*)u1, (const float4*)r1,
                                off_r, csr_r, off_u, csr_u,
                                (float4*)mr, (float4*)mu);
    {
        DualArgs d;
        d.A0 = mr; d.X0 = r1; d.Wl0 = wt + WT_C2URWL; d.bl0 = c2_ur_bl;
        d.Wr0 = wt + WT_C2URWR; d.Y0 = zr; d.M0 = NR; d.g0 = GR;
        d.A1 = mu; d.X1 = u1; d.Wl1 = wt + WT_C2RUWL; d.bl1 = c2_ru_bl;
        d.Wr1 = wt + WT_C2RUWR; d.Y1 = zu; d.M1 = NU;
        gemm_dual2<64, 128, false><<<GR + GU, 256, S_D64>>>(d);
    }

    // ---- decoder ----
    decode_kernel<<<(NL * 32 + 255) / 256, 256>>>(zu, zr, lbl_src, lbl_dst, out, NL);
}

// round 3
// speedup vs baseline: 1.5544x; 1.3949x over previous
#include <cuda_runtime.h>
#include <cuda_bf16.h>
#include <math.h>

#define NU 100000
#define NR 50000
#define NE 600000
#define NL 200000
#define HD 128
#define OD 64

typedef unsigned long long u64;

// ---------------- f32x2 packed math ----------------
__device__ __forceinline__ u64 fma2(u64 a, u64 b, u64 c) {
    u64 d;
    asm("fma.rn.f32x2 %0, %1, %2, %3;" : "=l"(d) : "l"(a), "l"(b), "l"(c));
    return d;
}
__device__ __forceinline__ u64 pack2(float x, float y) {
    u64 d; asm("mov.b64 %0, {%1, %2};" : "=l"(d) : "f"(x), "f"(y)); return d;
}
__device__ __forceinline__ float2 unpack2(u64 v) {
    float2 r; asm("mov.b64 {%0, %1}, %2;" : "=f"(r.x), "=f"(r.y) : "l"(v)); return r;
}

// ---------------- scratch ----------------
__device__ __align__(16) float g_hu[(size_t)NU * HD];
__device__ __align__(16) float g_hr[(size_t)NR * HD];
__device__ __align__(16) float g_p1[(size_t)NR * HD];     // hr @ c1_ru_Wl^T
__device__ __align__(16) float g_u1[(size_t)NU * HD];
__device__ __align__(16) float g_r1[(size_t)NR * HD];
__device__ __align__(16) float g_mean_u[(size_t)NU * HD]; // gather results (128-d)
__device__ __align__(16) float g_mean_r[(size_t)NR * HD];
__device__ __align__(16) float g_t[(size_t)NU * OD];      // u1 @ c2_ur_Wl^T
__device__ __align__(16) float g_q[(size_t)NR * OD];      // r1 @ c2_ru_Wl^T
__device__ __align__(16) float g_mr2[(size_t)NR * OD];
__device__ __align__(16) float g_mu2[(size_t)NU * OD];
__device__ __align__(16) float g_zu[(size_t)NU * OD];
__device__ __align__(16) float g_zr[(size_t)NR * OD];
__device__ __align__(16) float g_wt[147456];

__device__ int g_deg_r[NR];
__device__ int g_deg_u[NU];
__device__ int g_off_r[NR + 1];
__device__ int g_off_u[NU + 1];
__device__ int g_cur_r[NR];
__device__ int g_cur_u[NU];
__device__ int g_csr_r[NE];
__device__ int g_csr_u[NE];

#define WT_WU      0
#define WT_WREC    16384
#define WT_C1URWL  49152
#define WT_C1URWR  65536
#define WT_C1RUWL  81920
#define WT_C1RUWR  98304
#define WT_C2URWL  114688
#define WT_C2URWR  122880
#define WT_C2RUWL  131072
#define WT_C2RUWR  139264

// ---------------- CSR build ----------------
__global__ void count_kernel(const int* __restrict__ es, const int* __restrict__ ed,
                             int* __restrict__ deg_u, int* __restrict__ deg_r, int E)
{
    int t = blockIdx.x * blockDim.x + threadIdx.x;
    if (t < E) {
        atomicAdd(&deg_u[es[t]], 1);
        atomicAdd(&deg_r[ed[t]], 1);
    }
}

// block 0 scans recipes, block 1 scans users
__global__ void scan2_kernel(const int* __restrict__ deg_r, int* __restrict__ off_r,
                             int* __restrict__ cur_r,
                             const int* __restrict__ deg_u, int* __restrict__ off_u,
                             int* __restrict__ cur_u)
{
    const int* deg; int* off; int* cur; int n;
    if (blockIdx.x == 0) { deg = deg_r; off = off_r; cur = cur_r; n = NR; }
    else                 { deg = deg_u; off = off_u; cur = cur_u; n = NU; }
    __shared__ int tmp[1024];
    int t = threadIdx.x;
    int chunk = (n + 1023) / 1024;
    int start = min(t * chunk, n);
    int end = min(start + chunk, n);
    int s = 0;
    for (int i = start; i < end; i++) s += deg[i];
    tmp[t] = s;
    __syncthreads();
    for (int d = 1; d < 1024; d <<= 1) {
        int v = (t >= d) ? tmp[t - d] : 0;
        __syncthreads();
        tmp[t] += v;
        __syncthreads();
    }
    int run = (t == 0) ? 0 : tmp[t - 1];
    for (int i = start; i < end; i++) {
        off[i] = run;
        cur[i] = run;
        run += deg[i];
    }
    if (end == n) off[n] = run;
}

__global__ void fill_kernel(const int* __restrict__ es, const int* __restrict__ ed,
                            int* __restrict__ cur_u, int* __restrict__ cur_r,
                            int* __restrict__ csr_u, int* __restrict__ csr_r, int E)
{
    int t = blockIdx.x * blockDim.x + threadIdx.x;
    if (t < E) {
        int s = es[t], d = ed[t];
        int pr = atomicAdd(&cur_r[d], 1);
        csr_r[pr] = s;
        int pu = atomicAdd(&cur_u[s], 1);
        csr_u[pu] = d;
    }
}

// ---------------- weight transpose ----------------
struct WtArgs {
    const float* src[10];
    int n[10];
    int k[10];
    int blk_off[11];
    int doff[10];
};

__global__ void wtrans_kernel(WtArgs a, float* __restrict__ dst)
{
    int b = blockIdx.x;
    int m = 0;
    while (b >= a.blk_off[m + 1]) m++;
    int idx = (b - a.blk_off[m]) * 256 + threadIdx.x;
    int N = a.n[m], K = a.k[m];
    if (idx < N * K) {
        int kk = idx / N, nn = idx - kk * N;
        dst[a.doff[m] + idx] = a.src[m][nn * K + kk];
    }
}

// ---------------- gather-mean 128-dim (both directions), warp/node ----------------
__global__ __launch_bounds__(256) void gather2_128(
    const float4* __restrict__ featR, const float4* __restrict__ featU,
    const int* __restrict__ off_r, const int* __restrict__ csr_r,
    const int* __restrict__ off_u, const int* __restrict__ csr_u,
    float4* __restrict__ outR, float4* __restrict__ outU)
{
    int warp = (blockIdx.x * blockDim.x + threadIdx.x) >> 5;
    int lane = threadIdx.x & 31;
    const float4* feat;
    const int* off;
    const int* csr;
    float4* outm;
    int node;
    if (warp < NR) {
        feat = featR; off = off_r; csr = csr_r; outm = outR; node = warp;
    } else if (warp < NR + NU) {
        feat = featU; off = off_u; csr = csr_u; outm = outU; node = warp - NR;
    } else return;
    int b = off[node], e = off[node + 1];
    float4 acc = make_float4(0.f, 0.f, 0.f, 0.f);
    for (int i = b; i < e; i++) {
        int nb = csr[i];
        float4 v = feat[(size_t)nb * 32 + lane];
        acc.x += v.x; acc.y += v.y; acc.z += v.z; acc.w += v.w;
    }
    float inv = 1.f / fmaxf((float)(e - b), 1.f);
    acc.x *= inv; acc.y *= inv; acc.z *= inv; acc.w *= inv;
    outm[(size_t)node * 32 + lane] = acc;
}

// ---------------- gather-mean 64-dim (both directions), warp/node ----------------
__global__ __launch_bounds__(256) void gather2_64(
    const float2* __restrict__ featR, const float2* __restrict__ featU,
    const int* __restrict__ off_r, const int* __restrict__ csr_r,
    const int* __restrict__ off_u, const int* __restrict__ csr_u,
    float2* __restrict__ outR, float2* __restrict__ outU)
{
    int warp = (blockIdx.x * blockDim.x + threadIdx.x) >> 5;
    int lane = threadIdx.x & 31;
    const float2* feat;
    const int* off;
    const int* csr;
    float2* outm;
    int node;
    if (warp < NR) {
        feat = featR; off = off_r; csr = csr_r; outm = outR; node = warp;
    } else if (warp < NR + NU) {
        feat = featU; off = off_u; csr = csr_u; outm = outU; node = warp - NR;
    } else return;
    int b = off[node], e = off[node + 1];
    float2 acc = make_float2(0.f, 0.f);
    for (int i = b; i < e; i++) {
        int nb = csr[i];
        float2 v = feat[(size_t)nb * 32 + lane];
        acc.x += v.x; acc.y += v.y;
    }
    float inv = 1.f / fmaxf((float)(e - b), 1.f);
    acc.x *= inv; acc.y *= inv;
    outm[(size_t)node * 32 + lane] = acc;
}

// ---------------- persistent GEMM (f32x2) ----------------
// Y[M,N] = (ADDIN ? ADD : 0) + (HASB ? bl : 0) + A@Wlt (+ X@Wrt if DUAL) (+relu)
// Wlt pre-transposed [K][N]. Weights staged ONCE per block; tiles loop.
template <int N, int K, bool DUAL, bool ADDIN, bool HASB, bool RELU>
__global__ __launch_bounds__(256) void gemm_k(
    const float* __restrict__ A, const float* __restrict__ X,
    const float* __restrict__ Wlt, const float* __restrict__ Wrt,
    const float* __restrict__ bl, const float* __restrict__ ADDP,
    float* __restrict__ Y, int M)
{
    constexpr int CPT = N / 32;
    constexpr int PAIRS = CPT / 2;
    extern __shared__ float sm[];
    float* sWl = sm;
    float* sWr = sm + K * N;
    float* sA  = sm + (DUAL ? 2 : 1) * K * N;
    float* sX  = sA + 64 * K;

    const int tid = threadIdx.x;

    // stage weights once (float4)
    {
        const float4* w4 = (const float4*)Wlt;
        float4* s4 = (float4*)sWl;
        for (int i = tid; i < K * N / 4; i += 256) s4[i] = w4[i];
        if (DUAL) {
            const float4* v4 = (const float4*)Wrt;
            float4* t4 = (float4*)sWr;
            for (int i = tid; i < K * N / 4; i += 256) t4[i] = v4[i];
        }
    }

    const int lane = tid & 31;
    const int w = tid >> 5;
    const int r0 = w * 8;
    const int colbase = lane * CPT;

    float bv[CPT];
#pragma unroll
    for (int j = 0; j < CPT; j++) bv[j] = HASB ? bl[colbase + j] : 0.f;

    const int ntiles = (M + 63) >> 6;
    for (int tile = blockIdx.x; tile < ntiles; tile += gridDim.x) {
        const int row0 = tile << 6;
        __syncthreads();  // protect sA from previous iteration's readers
        // stage A (and X), float4
        {
            int lim = min(64, M - row0) * (K / 4);
            const float4* A4 = (const float4*)(A + (size_t)row0 * K);
            float4* sA4 = (float4*)sA;
            const float4* X4 = DUAL ? (const float4*)(X + (size_t)row0 * K) : nullptr;
            float4* sX4 = (float4*)sX;
            for (int i = tid; i < 64 * K / 4; i += 256) {
                float4 v = (i < lim) ? A4[i] : make_float4(0.f, 0.f, 0.f, 0.f);
                sA4[i] = v;
                if (DUAL) {
                    float4 u = (i < lim) ? X4[i] : make_float4(0.f, 0.f, 0.f, 0.f);
                    sX4[i] = u;
                }
            }
        }
        __syncthreads();

        u64 acc[8][PAIRS];
#pragma unroll
        for (int i = 0; i < 8; i++)
#pragma unroll
            for (int p = 0; p < PAIRS; p++) acc[i][p] = 0ull;

#pragma unroll 2
        for (int k0 = 0; k0 < K; k0 += 4) {
            float4 a4[8], x4[8];
#pragma unroll
            for (int i = 0; i < 8; i++) {
                a4[i] = *(const float4*)&sA[(r0 + i) * K + k0];
                if (DUAL) x4[i] = *(const float4*)&sX[(r0 + i) * K + k0];
            }
#pragma unroll
            for (int kk = 0; kk < 4; kk++) {
                u64 wl[PAIRS], wr[PAIRS];
                const float* wlp = &sWl[(k0 + kk) * N + colbase];
                if (CPT == 4) {
                    float4 v = *(const float4*)wlp;
                    wl[0] = pack2(v.x, v.y);
                    if (PAIRS > 1) wl[1] = pack2(v.z, v.w);
                } else {
                    float2 v = *(const float2*)wlp;
                    wl[0] = pack2(v.x, v.y);
                }
                if (DUAL) {
                    const float* wrp = &sWr[(k0 + kk) * N + colbase];
                    if (CPT == 4) {
                        float4 v = *(const float4*)wrp;
                        wr[0] = pack2(v.x, v.y);
                        if (PAIRS > 1) wr[1] = pack2(v.z, v.w);
                    } else {
                        float2 v = *(const float2*)wrp;
                        wr[0] = pack2(v.x, v.y);
                    }
                }
#pragma unroll
                for (int i = 0; i < 8; i++) {
                    float as = (kk == 0) ? a4[i].x : (kk == 1) ? a4[i].y :
                               (kk == 2) ? a4[i].z : a4[i].w;
                    u64 a2 = pack2(as, as);
#pragma unroll
                    for (int p = 0; p < PAIRS; p++) acc[i][p] = fma2(a2, wl[p], acc[i][p]);
                    if (DUAL) {
                        float xs = (kk == 0) ? x4[i].x : (kk == 1) ? x4[i].y :
                                   (kk == 2) ? x4[i].z : x4[i].w;
                        u64 x2 = pack2(xs, xs);
#pragma unroll
                        for (int p = 0; p < PAIRS; p++) acc[i][p] = fma2(x2, wr[p], acc[i][p]);
                    }
                }
            }
        }

        // epilogue
#pragma unroll
        for (int i = 0; i < 8; i++) {
            int row = row0 + r0 + i;
            if (row < M) {
                float o[CPT];
#pragma unroll
                for (int p = 0; p < PAIRS; p++) {
                    float2 v = unpack2(acc[i][p]);
                    o[2 * p] = v.x + bv[2 * p];
                    o[2 * p + 1] = v.y + bv[2 * p + 1];
                }
                if (ADDIN) {
                    const float* ap = &ADDP[(size_t)row * N + colbase];
                    if (CPT == 4) {
                        float4 v = *(const float4*)ap;
                        o[0] += v.x; o[1] += v.y; o[2] += v.z; o[3] += v.w;
                    } else {
                        float2 v = *(const float2*)ap;
                        o[0] += v.x; o[1] += v.y;
                    }
                }
                if (RELU) {
#pragma unroll
                    for (int j = 0; j < CPT; j++) o[j] = fmaxf(o[j], 0.f);
                }
                float* yp = &Y[(size_t)row * N + colbase];
                if (CPT == 4) *(float4*)yp = make_float4(o[0], o[1], o[2], o[3]);
                else          *(float2*)yp = make_float2(o[0], o[1]);
            }
        }
    }
}

// ---------------- decoder ----------------
__global__ __launch_bounds__(256) void decode_kernel(
    const float2* __restrict__ zu, const float2* __restrict__ zr,
    const int* __restrict__ ls, const int* __restrict__ ld,
    float* __restrict__ out, int L)
{
    int warp = (blockIdx.x * blockDim.x + threadIdx.x) >> 5;
    int lane = threadIdx.x & 31;
    if (warp >= L) return;
    int s = ls[warp], d = ld[warp];
    float2 a = zu[(size_t)s * 32 + lane];
    float2 b = zr[(size_t)d * 32 + lane];
    float dot = a.x * b.x + a.y * b.y;
    float na = a.x * a.x + a.y * a.y;
    float nb = b.x * b.x + b.y * b.y;
#pragma unroll
    for (int o = 16; o; o >>= 1) {
        dot += __shfl_xor_sync(0xffffffffu, dot, o);
        na  += __shfl_xor_sync(0xffffffffu, na, o);
        nb  += __shfl_xor_sync(0xffffffffu, nb, o);
    }
    if (lane == 0)
        out[warp] = dot / (fmaxf(sqrtf(na), 1e-12f) * fmaxf(sqrtf(nb), 1e-12f));
}

// ---------------- host launch ----------------
extern "C" void kernel_launch(void* const* d_in, const int* in_sizes, int n_in,
                              void* d_out, int out_size)
{
    const float* x_user   = (const float*)d_in[0];
    const float* x_recipe = (const float*)d_in[1];
    const int* edge_src   = (const int*)d_in[2];
    const int* edge_dst   = (const int*)d_in[3];
    const int* lbl_src    = (const int*)d_in[4];
    const int* lbl_dst    = (const int*)d_in[5];
    const float* Wu   = (const float*)d_in[6];
    const float* bu   = (const float*)d_in[7];
    const float* Wrec = (const float*)d_in[8];
    const float* brec = (const float*)d_in[9];
    const float* c1_ur_Wl = (const float*)d_in[10];
    const float* c1_ur_bl = (const float*)d_in[11];
    const float* c1_ur_Wr = (const float*)d_in[12];
    const float* c1_ru_Wl = (const float*)d_in[13];
    const float* c1_ru_bl = (const float*)d_in[14];
    const float* c1_ru_Wr = (const float*)d_in[15];
    const float* c2_ur_Wl = (const float*)d_in[16];
    const float* c2_ur_bl = (const float*)d_in[17];
    const float* c2_ur_Wr = (const float*)d_in[18];
    const float* c2_ru_Wl = (const float*)d_in[19];
    const float* c2_ru_bl = (const float*)d_in[20];
    const float* c2_ru_Wr = (const float*)d_in[21];
    float* out = (float*)d_out;

    float *hu, *hr, *p1, *u1, *r1, *mu, *mr, *t, *q, *mr2, *mu2, *zu, *zr, *wt;
    int *deg_r, *deg_u, *off_r, *off_u, *cur_r, *cur_u, *csr_r, *csr_u;
    cudaGetSymbolAddress((void**)&hu, g_hu);
    cudaGetSymbolAddress((void**)&hr, g_hr);
    cudaGetSymbolAddress((void**)&p1, g_p1);
    cudaGetSymbolAddress((void**)&u1, g_u1);
    cudaGetSymbolAddress((void**)&r1, g_r1);
    cudaGetSymbolAddress((void**)&mu, g_mean_u);
    cudaGetSymbolAddress((void**)&mr, g_mean_r);
    cudaGetSymbolAddress((void**)&t, g_t);
    cudaGetSymbolAddress((void**)&q, g_q);
    cudaGetSymbolAddress((void**)&mr2, g_mr2);
    cudaGetSymbolAddress((void**)&mu2, g_mu2);
    cudaGetSymbolAddress((void**)&zu, g_zu);
    cudaGetSymbolAddress((void**)&zr, g_zr);
    cudaGetSymbolAddress((void**)&wt, g_wt);
    cudaGetSymbolAddress((void**)&deg_r, g_deg_r);
    cudaGetSymbolAddress((void**)&deg_u, g_deg_u);
    cudaGetSymbolAddress((void**)&off_r, g_off_r);
    cudaGetSymbolAddress((void**)&off_u, g_off_u);
    cudaGetSymbolAddress((void**)&cur_r, g_cur_r);
    cudaGetSymbolAddress((void**)&cur_u, g_cur_u);
    cudaGetSymbolAddress((void**)&csr_r, g_csr_r);
    cudaGetSymbolAddress((void**)&csr_u, g_csr_u);

    // smem sizes
    const int S_P128 = (128 * 128 + 64 * 128) * 4;           // 98304
    const int S_P256 = (256 * 128 + 64 * 256) * 4;           // 196608
    const int S_D128 = (2 * 128 * 128 + 2 * 64 * 128) * 4;   // 196608
    const int S_P64  = (128 * 64 + 64 * 128) * 4;            // 65536

    cudaFuncSetAttribute((gemm_k<128, 128, false, false, true,  false>),
                         cudaFuncAttributeMaxDynamicSharedMemorySize, S_P128);
    cudaFuncSetAttribute((gemm_k<128, 256, false, false, true,  false>),
                         cudaFuncAttributeMaxDynamicSharedMemorySize, S_P256);
    cudaFuncSetAttribute((gemm_k<128, 128, false, false, false, false>),
                         cudaFuncAttributeMaxDynamicSharedMemorySize, S_P128);
    cudaFuncSetAttribute((gemm_k<128, 128, true,  false, true,  true>),
                         cudaFuncAttributeMaxDynamicSharedMemorySize, S_D128);
    cudaFuncSetAttribute((gemm_k<128, 128, false, true,  true,  true>),
                         cudaFuncAttributeMaxDynamicSharedMemorySize, S_P128);
    cudaFuncSetAttribute((gemm_k<64, 128, false, false, false, false>),
                         cudaFuncAttributeMaxDynamicSharedMemorySize, S_P64);
    cudaFuncSetAttribute((gemm_k<64, 128, false, true,  true,  false>),
                         cudaFuncAttributeMaxDynamicSharedMemorySize, S_P64);

    // ---- CSR build ----
    cudaMemsetAsync(deg_r, 0, NR * sizeof(int), 0);
    cudaMemsetAsync(deg_u, 0, NU * sizeof(int), 0);
    count_kernel<<<(NE + 255) / 256, 256>>>(edge_src, edge_dst, deg_u, deg_r, NE);
    scan2_kernel<<<2, 1024>>>(deg_r, off_r, cur_r, deg_u, off_u, cur_u);
    fill_kernel<<<(NE + 255) / 256, 256>>>(edge_src, edge_dst, cur_u, cur_r,
                                           csr_u, csr_r, NE);

    // ---- weight transpose ----
    {
        WtArgs a;
        const float* srcs[10] = {Wu, Wrec, c1_ur_Wl, c1_ur_Wr, c1_ru_Wl, c1_ru_Wr,
                                 c2_ur_Wl, c2_ur_Wr, c2_ru_Wl, c2_ru_Wr};
        int ns[10] = {128, 128, 128, 128, 128, 128, 64, 64, 64, 64};
        int ks[10] = {128, 256, 128, 128, 128, 128, 128, 128, 128, 128};
        int doffs[10] = {WT_WU, WT_WREC, WT_C1URWL, WT_C1URWR, WT_C1RUWL, WT_C1RUWR,
                         WT_C2URWL, WT_C2URWR, WT_C2RUWL, WT_C2RUWR};
        int boff = 0;
        for (int m = 0; m < 10; m++) {
            a.src[m] = srcs[m]; a.n[m] = ns[m]; a.k[m] = ks[m]; a.doff[m] = doffs[m];
            a.blk_off[m] = boff;
            boff += (ns[m] * ks[m] + 255) / 256;
        }
        a.blk_off[10] = boff;
        wtrans_kernel<<<boff, 256>>>(a, wt);
    }

    // ---- projections ----
    gemm_k<128, 128, false, false, true, false><<<296, 256, S_P128>>>(
        x_user, nullptr, wt + WT_WU, nullptr, bu, nullptr, hu, NU);
    gemm_k<128, 256, false, false, true, false><<<148, 256, S_P256>>>(
        x_recipe, nullptr, wt + WT_WREC, nullptr, brec, nullptr, hr, NR);
    // p1 = hr @ c1_ru_Wl^T (project-first, r->u direction; no bias)
    gemm_k<128, 128, false, false, false, false><<<296, 256, S_P128>>>(
        hr, nullptr, wt + WT_C1RUWL, nullptr, nullptr, nullptr, p1, NR);

    const int GW = ((NR + NU) * 32 + 255) / 256;

    // ---- conv1 ----
    // mr = mean over recipe's neighbors of hu; mu = mean over user's neighbors of p1
    gather2_128<<<GW, 256>>>((const float4*)hu, (const float4*)p1,
                             off_r, csr_r, off_u, csr_u,
                             (float4*)mr, (float4*)mu);
    // r1 = relu(mr@Wl + bl + hr@Wr)
    gemm_k<128, 128, true, false, true, true><<<148, 256, S_D128>>>(
        mr, hr, wt + WT_C1URWL, wt + WT_C1URWR, c1_ur_bl, nullptr, r1, NR);
    // u1 = relu(mu + bl + hu@Wr)
    gemm_k<128, 128, false, true, true, true><<<296, 256, S_P128>>>(
        hu, nullptr, wt + WT_C1RUWR, nullptr, c1_ru_bl, mu, u1, NU);

    // ---- conv2 (project-first both directions to 64-d) ----
    gemm_k<64, 128, false, false, false, false><<<444, 256, S_P64>>>(
        u1, nullptr, wt + WT_C2URWL, nullptr, nullptr, nullptr, t, NU);
    gemm_k<64, 128, false, false, false, false><<<444, 256, S_P64>>>(
        r1, nullptr, wt + WT_C2RUWL, nullptr, nullptr, nullptr, q, NR);
    gather2_64<<<GW, 256>>>((const float2*)t, (const float2*)q,
                            off_r, csr_r, off_u, csr_u,
                            (float2*)mr2, (float2*)mu2);
    // zr = mr2 + bl + r1@Wr ; zu = mu2 + bl + u1@Wr
    gemm_k<64, 128, false, true, true, false><<<444, 256, S_P64>>>(
        r1, nullptr, wt + WT_C2URWR, nullptr, c2_ur_bl, mr2, zr, NR);
    gemm_k<64, 128, false, true, true, false><<<444, 256, S_P64>>>(
        u1, nullptr, wt + WT_C2RUWR, nullptr, c2_ru_bl, mu2, zu, NU);

    // ---- decoder ----
    decode_kernel<<<(NL * 32 + 255) / 256, 256>>>(
        (const float2*)zu, (const float2*)zr, lbl_src, lbl_dst, out, NL);
}

// round 4
// speedup vs baseline: 1.8827x; 1.2112x over previous
#include <cuda_runtime.h>
#include <cuda_bf16.h>
#include <math.h>

#define NU 100000
#define NR 50000
#define NE 600000
#define NL 200000
#define HD 128
#define OD 64

typedef unsigned long long u64;

// ---------------- f32x2 packed math ----------------
__device__ __forceinline__ u64 fma2(u64 a, u64 b, u64 c) {
    u64 d;
    asm("fma.rn.f32x2 %0, %1, %2, %3;" : "=l"(d) : "l"(a), "l"(b), "l"(c));
    return d;
}
__device__ __forceinline__ u64 pack2(float x, float y) {
    u64 d; asm("mov.b64 %0, {%1, %2};" : "=l"(d) : "f"(x), "f"(y)); return d;
}
__device__ __forceinline__ float2 unpack2(u64 v) {
    float2 r; asm("mov.b64 {%0, %1}, %2;" : "=f"(r.x), "=f"(r.y) : "l"(v)); return r;
}

// ---------------- scratch ----------------
__device__ __align__(16) float g_hu[(size_t)NU * HD];
__device__ __align__(16) float g_hr[(size_t)NR * HD];
__device__ __align__(16) float g_p1[(size_t)NR * HD];     // hr @ c1_ru_Wl^T
__device__ __align__(16) float g_u1[(size_t)NU * HD];
__device__ __align__(16) float g_r1[(size_t)NR * HD];
__device__ __align__(16) float g_mean_u[(size_t)NU * HD]; // mu, then reused as U2
__device__ __align__(16) float g_mean_r[(size_t)NR * HD]; // mr, then reused as R2
__device__ __align__(16) float g_zu[(size_t)NU * OD];
__device__ __align__(16) float g_zr[(size_t)NR * OD];
__device__ __align__(16) float g_wt[147456];

__device__ int g_deg_r[NR];
__device__ int g_deg_u[NU];
__device__ int g_off_r[NR + 1];
__device__ int g_off_u[NU + 1];
__device__ int g_cur_r[NR];
__device__ int g_cur_u[NU];
__device__ int g_csr_r[NE];
__device__ int g_csr_u[NE];

#define WT_WU      0
#define WT_WREC    16384
#define WT_C1URWL  49152
#define WT_C1URWR  65536
#define WT_C1RUWL  81920
#define WT_C1RUWR  98304
#define WT_U2      114688   // [K=128][N=128]: cols 0-63 c2_ur_Wl^T, 64-127 c2_ru_Wr^T
#define WT_R2      131072   // [K=128][N=128]: cols 0-63 c2_ru_Wl^T, 64-127 c2_ur_Wr^T

// ---------------- CSR build ----------------
__global__ void count_kernel(const int* __restrict__ es, const int* __restrict__ ed,
                             int* __restrict__ deg_u, int* __restrict__ deg_r, int E)
{
    int t = blockIdx.x * blockDim.x + threadIdx.x;
    if (t < E) {
        atomicAdd(&deg_u[es[t]], 1);
        atomicAdd(&deg_r[ed[t]], 1);
    }
}

__global__ void scan2_kernel(const int* __restrict__ deg_r, int* __restrict__ off_r,
                             int* __restrict__ cur_r,
                             const int* __restrict__ deg_u, int* __restrict__ off_u,
                             int* __restrict__ cur_u)
{
    const int* deg; int* off; int* cur; int n;
    if (blockIdx.x == 0) { deg = deg_r; off = off_r; cur = cur_r; n = NR; }
    else                 { deg = deg_u; off = off_u; cur = cur_u; n = NU; }
    __shared__ int tmp[1024];
    int t = threadIdx.x;
    int chunk = (n + 1023) / 1024;
    int start = min(t * chunk, n);
    int end = min(start + chunk, n);
    int s = 0;
    for (int i = start; i < end; i++) s += deg[i];
    tmp[t] = s;
    __syncthreads();
    for (int d = 1; d < 1024; d <<= 1) {
        int v = (t >= d) ? tmp[t - d] : 0;
        __syncthreads();
        tmp[t] += v;
        __syncthreads();
    }
    int run = (t == 0) ? 0 : tmp[t - 1];
    for (int i = start; i < end; i++) {
        off[i] = run;
        cur[i] = run;
        run += deg[i];
    }
    if (end == n) off[n] = run;
}

__global__ void fill_kernel(const int* __restrict__ es, const int* __restrict__ ed,
                            int* __restrict__ cur_u, int* __restrict__ cur_r,
                            int* __restrict__ csr_u, int* __restrict__ csr_r, int E)
{
    int t = blockIdx.x * blockDim.x + threadIdx.x;
    if (t < E) {
        int s = es[t], d = ed[t];
        int pr = atomicAdd(&cur_r[d], 1);
        csr_r[pr] = s;
        int pu = atomicAdd(&cur_u[s], 1);
        csr_u[pu] = d;
    }
}

// ---------------- weight transpose (with dst pitch + column offset) ----------------
struct WtArgs {
    const float* src[10];
    int n[10];
    int k[10];
    int dstN[10];
    int coloff[10];
    int doff[10];
    int blk_off[11];
};

__global__ void wtrans_kernel(WtArgs a, float* __restrict__ dst)
{
    int b = blockIdx.x;
    int m = 0;
    while (b >= a.blk_off[m + 1]) m++;
    int idx = (b - a.blk_off[m]) * 256 + threadIdx.x;
    int N = a.n[m], K = a.k[m];
    if (idx < N * K) {
        int kk = idx / N, nn = idx - kk * N;
        dst[a.doff[m] + kk * a.dstN[m] + a.coloff[m] + nn] = a.src[m][nn * K + kk];
    }
}

// ---------------- gather-mean 128-dim (both directions), warp/node, unroll-4 ----------------
__global__ __launch_bounds__(256) void gather2_128(
    const float4* __restrict__ featR, const float4* __restrict__ featU,
    const int* __restrict__ off_r, const int* __restrict__ csr_r,
    const int* __restrict__ off_u, const int* __restrict__ csr_u,
    float4* __restrict__ outR, float4* __restrict__ outU)
{
    int warp = (blockIdx.x * blockDim.x + threadIdx.x) >> 5;
    int lane = threadIdx.x & 31;
    const float4* feat;
    const int* off;
    const int* csr;
    float4* outm;
    int node;
    if (warp < NR) {
        feat = featR; off = off_r; csr = csr_r; outm = outR; node = warp;
    } else if (warp < NR + NU) {
        feat = featU; off = off_u; csr = csr_u; outm = outU; node = warp - NR;
    } else return;
    int b = off[node], e = off[node + 1];
    float4 acc = make_float4(0.f, 0.f, 0.f, 0.f);
    int i = b;
    for (; i + 4 <= e; i += 4) {
        int n0 = csr[i], n1 = csr[i + 1], n2 = csr[i + 2], n3 = csr[i + 3];
        float4 v0 = feat[(size_t)n0 * 32 + lane];
        float4 v1 = feat[(size_t)n1 * 32 + lane];
        float4 v2 = feat[(size_t)n2 * 32 + lane];
        float4 v3 = feat[(size_t)n3 * 32 + lane];
        acc.x += v0.x + v1.x + v2.x + v3.x;
        acc.y += v0.y + v1.y + v2.y + v3.y;
        acc.z += v0.z + v1.z + v2.z + v3.z;
        acc.w += v0.w + v1.w + v2.w + v3.w;
    }
    for (; i < e; i++) {
        int nb = csr[i];
        float4 v = feat[(size_t)nb * 32 + lane];
        acc.x += v.x; acc.y += v.y; acc.z += v.z; acc.w += v.w;
    }
    float inv = 1.f / fmaxf((float)(e - b), 1.f);
    acc.x *= inv; acc.y *= inv; acc.z *= inv; acc.w *= inv;
    outm[(size_t)node * 32 + lane] = acc;
}

// ---------------- fused 64-dim gather + bias + root-term (conv2 epilogue) ----------------
// zr[node] = mean_{nb in csr_r} U2[nb].t + c2_ur_bl + R2[node].s
// zu[node] = mean_{nb in csr_u} R2[nb].q + c2_ru_bl + U2[node].s
// U2/R2 rows: 128 floats = 64 float2; cols 0-63 = proj part, 64-127 = root part.
__global__ __launch_bounds__(256) void gather2_64f(
    const float2* __restrict__ U2, const float2* __restrict__ R2,
    const float* __restrict__ bl_ur, const float* __restrict__ bl_ru,
    const int* __restrict__ off_r, const int* __restrict__ csr_r,
    const int* __restrict__ off_u, const int* __restrict__ csr_u,
    float2* __restrict__ zr, float2* __restrict__ zu)
{
    int warp = (blockIdx.x * blockDim.x + threadIdx.x) >> 5;
    int lane = threadIdx.x & 31;
    const float2* feat;
    const float2* selfp;
    const float2* bl;
    const int* off;
    const int* csr;
    float2* outp;
    int node;
    if (warp < NR) {
        node = warp;
        feat = U2; selfp = R2; bl = (const float2*)bl_ur;
        off = off_r; csr = csr_r; outp = zr;
    } else if (warp < NR + NU) {
        node = warp - NR;
        feat = R2; selfp = U2; bl = (const float2*)bl_ru;
        off = off_u; csr = csr_u; outp = zu;
    } else return;
    int b = off[node], e = off[node + 1];
    float2 acc = make_float2(0.f, 0.f);
    int i = b;
    for (; i + 4 <= e; i += 4) {
        int n0 = csr[i], n1 = csr[i + 1], n2 = csr[i + 2], n3 = csr[i + 3];
        float2 v0 = feat[(size_t)n0 * 64 + lane];
        float2 v1 = feat[(size_t)n1 * 64 + lane];
        float2 v2 = feat[(size_t)n2 * 64 + lane];
        float2 v3 = feat[(size_t)n3 * 64 + lane];
        acc.x += v0.x + v1.x + v2.x + v3.x;
        acc.y += v0.y + v1.y + v2.y + v3.y;
    }
    for (; i < e; i++) {
        int nb = csr[i];
        float2 v = feat[(size_t)nb * 64 + lane];
        acc.x += v.x; acc.y += v.y;
    }
    float inv = 1.f / fmaxf((float)(e - b), 1.f);
    float2 s = selfp[(size_t)node * 64 + 32 + lane];
    float2 bb = bl[lane];
    float2 o;
    o.x = acc.x * inv + bb.x + s.x;
    o.y = acc.y * inv + bb.y + s.y;
    outp[(size_t)node * 32 + lane] = o;
}

// ---------------- persistent GEMM (f32x2) ----------------
template <int N, int K, bool DUAL, bool ADDIN, bool HASB, bool RELU>
__global__ __launch_bounds__(256) void gemm_k(
    const float* __restrict__ A, const float* __restrict__ X,
    const float* __restrict__ Wlt, const float* __restrict__ Wrt,
    const float* __restrict__ bl, const float* __restrict__ ADDP,
    float* __restrict__ Y, int M)
{
    constexpr int CPT = N / 32;
    constexpr int PAIRS = CPT / 2;
    extern __shared__ float sm[];
    float* sWl = sm;
    float* sWr = sm + K * N;
    float* sA  = sm + (DUAL ? 2 : 1) * K * N;
    float* sX  = sA + 64 * K;

    const int tid = threadIdx.x;

    {
        const float4* w4 = (const float4*)Wlt;
        float4* s4 = (float4*)sWl;
        for (int i = tid; i < K * N / 4; i += 256) s4[i] = w4[i];
        if (DUAL) {
            const float4* v4 = (const float4*)Wrt;
            float4* t4 = (float4*)sWr;
            for (int i = tid; i < K * N / 4; i += 256) t4[i] = v4[i];
        }
    }

    const int lane = tid & 31;
    const int w = tid >> 5;
    const int r0 = w * 8;
    const int colbase = lane * CPT;

    float bv[CPT];
#pragma unroll
    for (int j = 0; j < CPT; j++) bv[j] = HASB ? bl[colbase + j] : 0.f;

    const int ntiles = (M + 63) >> 6;
    for (int tile = blockIdx.x; tile < ntiles; tile += gridDim.x) {
        const int row0 = tile << 6;
        __syncthreads();
        {
            int lim = min(64, M - row0) * (K / 4);
            const float4* A4 = (const float4*)(A + (size_t)row0 * K);
            float4* sA4 = (float4*)sA;
            const float4* X4 = DUAL ? (const float4*)(X + (size_t)row0 * K) : nullptr;
            float4* sX4 = (float4*)sX;
            for (int i = tid; i < 64 * K / 4; i += 256) {
                float4 v = (i < lim) ? A4[i] : make_float4(0.f, 0.f, 0.f, 0.f);
                sA4[i] = v;
                if (DUAL) {
                    float4 u = (i < lim) ? X4[i] : make_float4(0.f, 0.f, 0.f, 0.f);
                    sX4[i] = u;
                }
            }
        }
        __syncthreads();

        u64 acc[8][PAIRS];
#pragma unroll
        for (int i = 0; i < 8; i++)
#pragma unroll
            for (int p = 0; p < PAIRS; p++) acc[i][p] = 0ull;

#pragma unroll 2
        for (int k0 = 0; k0 < K; k0 += 4) {
            float4 a4[8], x4[8];
#pragma unroll
            for (int i = 0; i < 8; i++) {
                a4[i] = *(const float4*)&sA[(r0 + i) * K + k0];
                if (DUAL) x4[i] = *(const float4*)&sX[(r0 + i) * K + k0];
            }
#pragma unroll
            for (int kk = 0; kk < 4; kk++) {
                u64 wl[PAIRS], wr[PAIRS];
                const float* wlp = &sWl[(k0 + kk) * N + colbase];
                if (CPT == 4) {
                    float4 v = *(const float4*)wlp;
                    wl[0] = pack2(v.x, v.y);
                    if (PAIRS > 1) wl[1] = pack2(v.z, v.w);
                } else {
                    float2 v = *(const float2*)wlp;
                    wl[0] = pack2(v.x, v.y);
                }
                if (DUAL) {
                    const float* wrp = &sWr[(k0 + kk) * N + colbase];
                    if (CPT == 4) {
                        float4 v = *(const float4*)wrp;
                        wr[0] = pack2(v.x, v.y);
                        if (PAIRS > 1) wr[1] = pack2(v.z, v.w);
                    } else {
                        float2 v = *(const float2*)wrp;
                        wr[0] = pack2(v.x, v.y);
                    }
                }
#pragma unroll
                for (int i = 0; i < 8; i++) {
                    float as = (kk == 0) ? a4[i].x : (kk == 1) ? a4[i].y :
                               (kk == 2) ? a4[i].z : a4[i].w;
                    u64 a2 = pack2(as, as);
#pragma unroll
                    for (int p = 0; p < PAIRS; p++) acc[i][p] = fma2(a2, wl[p], acc[i][p]);
                    if (DUAL) {
                        float xs = (kk == 0) ? x4[i].x : (kk == 1) ? x4[i].y :
                                   (kk == 2) ? x4[i].z : x4[i].w;
                        u64 x2 = pack2(xs, xs);
#pragma unroll
                        for (int p = 0; p < PAIRS; p++) acc[i][p] = fma2(x2, wr[p], acc[i][p]);
                    }
                }
            }
        }

#pragma unroll
        for (int i = 0; i < 8; i++) {
            int row = row0 + r0 + i;
            if (row < M) {
                float o[CPT];
#pragma unroll
                for (int p = 0; p < PAIRS; p++) {
                    float2 v = unpack2(acc[i][p]);
                    o[2 * p] = v.x + bv[2 * p];
                    o[2 * p + 1] = v.y + bv[2 * p + 1];
                }
                if (ADDIN) {
                    const float* ap = &ADDP[(size_t)row * N + colbase];
                    if (CPT == 4) {
                        float4 v = *(const float4*)ap;
                        o[0] += v.x; o[1] += v.y; o[2] += v.z; o[3] += v.w;
                    } else {
                        float2 v = *(const float2*)ap;
                        o[0] += v.x; o[1] += v.y;
                    }
                }
                if (RELU) {
#pragma unroll
                    for (int j = 0; j < CPT; j++) o[j] = fmaxf(o[j], 0.f);
                }
                float* yp = &Y[(size_t)row * N + colbase];
                if (CPT == 4) *(float4*)yp = make_float4(o[0], o[1], o[2], o[3]);
                else          *(float2*)yp = make_float2(o[0], o[1]);
            }
        }
    }
}

// ---------------- decoder ----------------
__global__ __launch_bounds__(256) void decode_kernel(
    const float2* __restrict__ zu, const float2* __restrict__ zr,
    const int* __restrict__ ls, const int* __restrict__ ld,
    float* __restrict__ out, int L)
{
    int warp = (blockIdx.x * blockDim.x + threadIdx.x) >> 5;
    int lane = threadIdx.x & 31;
    if (warp >= L) return;
    int s = ls[warp], d = ld[warp];
    float2 a = zu[(size_t)s * 32 + lane];
    float2 b = zr[(size_t)d * 32 + lane];
    float dot = a.x * b.x + a.y * b.y;
    float na = a.x * a.x + a.y * a.y;
    float nb = b.x * b.x + b.y * b.y;
#pragma unroll
    for (int o = 16; o; o >>= 1) {
        dot += __shfl_xor_sync(0xffffffffu, dot, o);
        na  += __shfl_xor_sync(0xffffffffu, na, o);
        nb  += __shfl_xor_sync(0xffffffffu, nb, o);
    }
    if (lane == 0)
        out[warp] = dot / (fmaxf(sqrtf(na), 1e-12f) * fmaxf(sqrtf(nb), 1e-12f));
}

// ---------------- host launch ----------------
extern "C" void kernel_launch(void* const* d_in, const int* in_sizes, int n_in,
                              void* d_out, int out_size)
{
    const float* x_user   = (const float*)d_in[0];
    const float* x_recipe = (const float*)d_in[1];
    const int* edge_src   = (const int*)d_in[2];
    const int* edge_dst   = (const int*)d_in[3];
    const int* lbl_src    = (const int*)d_in[4];
    const int* lbl_dst    = (const int*)d_in[5];
    const float* Wu   = (const float*)d_in[6];
    const float* bu   = (const float*)d_in[7];
    const float* Wrec = (const float*)d_in[8];
    const float* brec = (const float*)d_in[9];
    const float* c1_ur_Wl = (const float*)d_in[10];
    const float* c1_ur_bl = (const float*)d_in[11];
    const float* c1_ur_Wr = (const float*)d_in[12];
    const float* c1_ru_Wl = (const float*)d_in[13];
    const float* c1_ru_bl = (const float*)d_in[14];
    const float* c1_ru_Wr = (const float*)d_in[15];
    const float* c2_ur_Wl = (const float*)d_in[16];
    const float* c2_ur_bl = (const float*)d_in[17];
    const float* c2_ur_Wr = (const float*)d_in[18];
    const float* c2_ru_Wl = (const float*)d_in[19];
    const float* c2_ru_bl = (const float*)d_in[20];
    const float* c2_ru_Wr = (const float*)d_in[21];
    float* out = (float*)d_out;

    float *hu, *hr, *p1, *u1, *r1, *mu, *mr, *zu, *zr, *wt;
    int *deg_r, *deg_u, *off_r, *off_u, *cur_r, *cur_u, *csr_r, *csr_u;
    cudaGetSymbolAddress((void**)&hu, g_hu);
    cudaGetSymbolAddress((void**)&hr, g_hr);
    cudaGetSymbolAddress((void**)&p1, g_p1);
    cudaGetSymbolAddress((void**)&u1, g_u1);
    cudaGetSymbolAddress((void**)&r1, g_r1);
    cudaGetSymbolAddress((void**)&mu, g_mean_u);
    cudaGetSymbolAddress((void**)&mr, g_mean_r);
    cudaGetSymbolAddress((void**)&zu, g_zu);
    cudaGetSymbolAddress((void**)&zr, g_zr);
    cudaGetSymbolAddress((void**)&wt, g_wt);
    cudaGetSymbolAddress((void**)&deg_r, g_deg_r);
    cudaGetSymbolAddress((void**)&deg_u, g_deg_u);
    cudaGetSymbolAddress((void**)&off_r, g_off_r);
    cudaGetSymbolAddress((void**)&off_u, g_off_u);
    cudaGetSymbolAddress((void**)&cur_r, g_cur_r);
    cudaGetSymbolAddress((void**)&cur_u, g_cur_u);
    cudaGetSymbolAddress((void**)&csr_r, g_csr_r);
    cudaGetSymbolAddress((void**)&csr_u, g_csr_u);

    // one-time side stream + events (created on first, uncaptured, call)
    static cudaStream_t side = nullptr;
    static cudaEvent_t evF = nullptr, evJ = nullptr;
    if (side == nullptr) {
        cudaStreamCreateWithFlags(&side, cudaStreamNonBlocking);
        cudaEventCreateWithFlags(&evF, cudaEventDisableTiming);
        cudaEventCreateWithFlags(&evJ, cudaEventDisableTiming);
    }

    // smem sizes
    const int S_P128 = (128 * 128 + 64 * 128) * 4;           // 98304
    const int S_P256 = (256 * 128 + 64 * 256) * 4;           // 196608
    const int S_D128 = (2 * 128 * 128 + 2 * 64 * 128) * 4;   // 196608

    cudaFuncSetAttribute((gemm_k<128, 128, false, false, true,  false>),
                         cudaFuncAttributeMaxDynamicSharedMemorySize, S_P128);
    cudaFuncSetAttribute((gemm_k<128, 256, false, false, true,  false>),
                         cudaFuncAttributeMaxDynamicSharedMemorySize, S_P256);
    cudaFuncSetAttribute((gemm_k<128, 128, false, false, false, false>),
                         cudaFuncAttributeMaxDynamicSharedMemorySize, S_P128);
    cudaFuncSetAttribute((gemm_k<128, 128, true,  false, true,  true>),
                         cudaFuncAttributeMaxDynamicSharedMemorySize, S_D128);
    cudaFuncSetAttribute((gemm_k<128, 128, false, true,  true,  true>),
                         cudaFuncAttributeMaxDynamicSharedMemorySize, S_P128);

    // ---- fork: CSR build on side stream ----
    cudaEventRecord(evF, 0);
    cudaStreamWaitEvent(side, evF, 0);
    cudaMemsetAsync(deg_r, 0, NR * sizeof(int), side);
    cudaMemsetAsync(deg_u, 0, NU * sizeof(int), side);
    count_kernel<<<(NE + 255) / 256, 256, 0, side>>>(edge_src, edge_dst, deg_u, deg_r, NE);
    scan2_kernel<<<2, 1024, 0, side>>>(deg_r, off_r, cur_r, deg_u, off_u, cur_u);
    fill_kernel<<<(NE + 255) / 256, 256, 0, side>>>(edge_src, edge_dst, cur_u, cur_r,
                                                    csr_u, csr_r, NE);
    cudaEventRecord(evJ, side);

    // ---- main stream: weight transpose + projections (independent of CSR) ----
    {
        WtArgs a;
        const float* srcs[10] = {Wu, Wrec, c1_ur_Wl, c1_ur_Wr, c1_ru_Wl, c1_ru_Wr,
                                 c2_ur_Wl, c2_ru_Wr, c2_ru_Wl, c2_ur_Wr};
        int ns[10]   = {128, 128, 128, 128, 128, 128, 64, 64, 64, 64};
        int ks[10]   = {128, 256, 128, 128, 128, 128, 128, 128, 128, 128};
        int dn[10]   = {128, 128, 128, 128, 128, 128, 128, 128, 128, 128};
        int co[10]   = {0, 0, 0, 0, 0, 0, 0, 64, 0, 64};
        int doffs[10] = {WT_WU, WT_WREC, WT_C1URWL, WT_C1URWR, WT_C1RUWL, WT_C1RUWR,
                         WT_U2, WT_U2, WT_R2, WT_R2};
        int boff = 0;
        for (int m = 0; m < 10; m++) {
            a.src[m] = srcs[m]; a.n[m] = ns[m]; a.k[m] = ks[m];
            a.dstN[m] = dn[m]; a.coloff[m] = co[m]; a.doff[m] = doffs[m];
            a.blk_off[m] = boff;
            boff += (ns[m] * ks[m] + 255) / 256;
        }
        a.blk_off[10] = boff;
        wtrans_kernel<<<boff, 256>>>(a, wt);
    }

    gemm_k<128, 128, false, false, true, false><<<296, 256, S_P128>>>(
        x_user, nullptr, wt + WT_WU, nullptr, bu, nullptr, hu, NU);
    gemm_k<128, 256, false, false, true, false><<<148, 256, S_P256>>>(
        x_recipe, nullptr, wt + WT_WREC, nullptr, brec, nullptr, hr, NR);
    gemm_k<128, 128, false, false, false, false><<<296, 256, S_P128>>>(
        hr, nullptr, wt + WT_C1RUWL, nullptr, nullptr, nullptr, p1, NR);

    // ---- join: gather needs CSR ----
    cudaStreamWaitEvent(0, evJ, 0);

    const int GW = ((NR + NU) * 32 + 255) / 256;

    // ---- conv1 ----
    gather2_128<<<GW, 256>>>((const float4*)hu, (const float4*)p1,
                             off_r, csr_r, off_u, csr_u,
                             (float4*)mr, (float4*)mu);
    gemm_k<128, 128, true, false, true, true><<<148, 256, S_D128>>>(
        mr, hr, wt + WT_C1URWL, wt + WT_C1URWR, c1_ur_bl, nullptr, r1, NR);
    gemm_k<128, 128, false, true, true, true><<<296, 256, S_P128>>>(
        hu, nullptr, wt + WT_C1RUWR, nullptr, c1_ru_bl, mu, u1, NU);

    // ---- conv2: combined projections then fused gather ----
    // U2 = u1 @ [c2_ur_Wl | c2_ru_Wr]^T   (reuses g_mean_u)
    gemm_k<128, 128, false, false, false, false><<<296, 256, S_P128>>>(
        u1, nullptr, wt + WT_U2, nullptr, nullptr, nullptr, mu, NU);
    // R2 = r1 @ [c2_ru_Wl | c2_ur_Wr]^T   (reuses g_mean_r)
    gemm_k<128, 128, false, false, false, false><<<296, 256, S_P128>>>(
        r1, nullptr, wt + WT_R2, nullptr, nullptr, nullptr, mr, NR);
    gather2_64f<<<GW, 256>>>((const float2*)mu, (const float2*)mr,
                             c2_ur_bl, c2_ru_bl,
                             off_r, csr_r, off_u, csr_u,
                             (float2*)zr, (float2*)zu);

    // ---- decoder ----
    decode_kernel<<<(NL * 32 + 255) / 256, 256>>>(
        (const float2*)zu, (const float2*)zr, lbl_src, lbl_dst, out, NL);
}